// round 1
// baseline (speedup 1.0000x reference)
#include <cuda_runtime.h>
#include <math.h>
#include <stdint.h>

#define B_  32
#define N_  512
#define M_  512
#define D_  1024

// Scratch (allocation-free rule: __device__ globals)
__device__ float g_S [(size_t)B_ * N_ * M_];   // align12 -> P12 (in place)
__device__ float g_St[(size_t)B_ * N_ * M_];   // align21 -> P21 (in place)

// ---------------------------------------------------------------------------
// GEMM NT: S[b, n, m] = sum_d x1[b,n,d] * x2[b,m,d]
// 128x128 block tile, BK=16, 256 threads, 8x8 per-thread tile.
// ---------------------------------------------------------------------------
__global__ __launch_bounds__(256, 2)
void gemm_nt_kernel(const float* __restrict__ X1,
                    const float* __restrict__ X2,
                    float* __restrict__ S)
{
    const int b  = blockIdx.z;
    const int n0 = blockIdx.y * 128;
    const int m0 = blockIdx.x * 128;

    const float* A  = X1 + (size_t)b * N_ * D_ + (size_t)n0 * D_;
    const float* Bp = X2 + (size_t)b * M_ * D_ + (size_t)m0 * D_;
    float*       Cp = S  + (size_t)b * N_ * M_;

    __shared__ float As[16][128];
    __shared__ float Bs[16][128];

    const int tid = threadIdx.x;
    const int tx  = tid & 15;   // column group (m)
    const int ty  = tid >> 4;   // row group (n)

    float acc[8][8];
#pragma unroll
    for (int i = 0; i < 8; i++)
#pragma unroll
        for (int j = 0; j < 8; j++) acc[i][j] = 0.f;

    for (int k0 = 0; k0 < D_; k0 += 16) {
#pragma unroll
        for (int l = 0; l < 2; l++) {
            int idx = tid + l * 256;     // 0..511
            int r   = idx >> 2;          // 0..127
            int c4  = idx & 3;           // 0..3  (k group of 4)
            float4 va = *reinterpret_cast<const float4*>(A  + (size_t)r * D_ + k0 + c4 * 4);
            float4 vb = *reinterpret_cast<const float4*>(Bp + (size_t)r * D_ + k0 + c4 * 4);
            As[c4 * 4 + 0][r] = va.x;  As[c4 * 4 + 1][r] = va.y;
            As[c4 * 4 + 2][r] = va.z;  As[c4 * 4 + 3][r] = va.w;
            Bs[c4 * 4 + 0][r] = vb.x;  Bs[c4 * 4 + 1][r] = vb.y;
            Bs[c4 * 4 + 2][r] = vb.z;  Bs[c4 * 4 + 3][r] = vb.w;
        }
        __syncthreads();

#pragma unroll
        for (int k = 0; k < 16; k++) {
            float a[8], bb[8];
            *reinterpret_cast<float4*>(&a[0])  = *reinterpret_cast<const float4*>(&As[k][ty * 8]);
            *reinterpret_cast<float4*>(&a[4])  = *reinterpret_cast<const float4*>(&As[k][ty * 8 + 4]);
            *reinterpret_cast<float4*>(&bb[0]) = *reinterpret_cast<const float4*>(&Bs[k][tx * 8]);
            *reinterpret_cast<float4*>(&bb[4]) = *reinterpret_cast<const float4*>(&Bs[k][tx * 8 + 4]);
#pragma unroll
            for (int i = 0; i < 8; i++)
#pragma unroll
                for (int j = 0; j < 8; j++)
                    acc[i][j] = fmaf(a[i], bb[j], acc[i][j]);
        }
        __syncthreads();
    }

#pragma unroll
    for (int i = 0; i < 8; i++) {
        int n = n0 + ty * 8 + i;
        float* crow = Cp + (size_t)n * M_ + m0 + tx * 8;
        *reinterpret_cast<float4*>(crow)     = make_float4(acc[i][0], acc[i][1], acc[i][2], acc[i][3]);
        *reinterpret_cast<float4*>(crow + 4) = make_float4(acc[i][4], acc[i][5], acc[i][6], acc[i][7]);
    }
}

// ---------------------------------------------------------------------------
// GEMM NN: C[b, r, d] = sum_k P[b, r, k] * X[b, k, d]
// rows = 512, K = 512, cols = 1024. Same tiling.
// ---------------------------------------------------------------------------
__global__ __launch_bounds__(256, 2)
void gemm_nn_kernel(const float* __restrict__ P,
                    const float* __restrict__ X,
                    float* __restrict__ C)
{
    const int b  = blockIdx.z;
    const int r0 = blockIdx.y * 128;   // output row
    const int d0 = blockIdx.x * 128;   // output col

    const float* A  = P + (size_t)b * 512 * 512 + (size_t)r0 * 512;
    const float* Bx = X + (size_t)b * 512 * D_;
    float*       Cp = C + (size_t)b * 512 * D_;

    __shared__ float As[16][128];   // transposed: As[k][row]
    __shared__ float Bs[16][128];   // natural:    Bs[k][col]

    const int tid = threadIdx.x;
    const int tx  = tid & 15;
    const int ty  = tid >> 4;

    float acc[8][8];
#pragma unroll
    for (int i = 0; i < 8; i++)
#pragma unroll
        for (int j = 0; j < 8; j++) acc[i][j] = 0.f;

    for (int k0 = 0; k0 < 512; k0 += 16) {
        // A tile: 128 rows x 16 k (K-contiguous)
#pragma unroll
        for (int l = 0; l < 2; l++) {
            int idx = tid + l * 256;
            int r   = idx >> 2;
            int c4  = idx & 3;
            float4 va = *reinterpret_cast<const float4*>(A + (size_t)r * 512 + k0 + c4 * 4);
            As[c4 * 4 + 0][r] = va.x;  As[c4 * 4 + 1][r] = va.y;
            As[c4 * 4 + 2][r] = va.z;  As[c4 * 4 + 3][r] = va.w;
        }
        // B tile: 16 k-rows x 128 d (d-contiguous)
#pragma unroll
        for (int l = 0; l < 2; l++) {
            int idx = tid + l * 256;     // 0..511 float4 slots
            int r   = idx >> 5;          // 0..15
            int c   = idx & 31;          // 0..31
            float4 vb = *reinterpret_cast<const float4*>(Bx + (size_t)(k0 + r) * D_ + d0 + c * 4);
            *reinterpret_cast<float4*>(&Bs[r][c * 4]) = vb;
        }
        __syncthreads();

#pragma unroll
        for (int k = 0; k < 16; k++) {
            float a[8], bb[8];
            *reinterpret_cast<float4*>(&a[0])  = *reinterpret_cast<const float4*>(&As[k][ty * 8]);
            *reinterpret_cast<float4*>(&a[4])  = *reinterpret_cast<const float4*>(&As[k][ty * 8 + 4]);
            *reinterpret_cast<float4*>(&bb[0]) = *reinterpret_cast<const float4*>(&Bs[k][tx * 8]);
            *reinterpret_cast<float4*>(&bb[4]) = *reinterpret_cast<const float4*>(&Bs[k][tx * 8 + 4]);
#pragma unroll
            for (int i = 0; i < 8; i++)
#pragma unroll
                for (int j = 0; j < 8; j++)
                    acc[i][j] = fmaf(a[i], bb[j], acc[i][j]);
        }
        __syncthreads();
    }

#pragma unroll
    for (int i = 0; i < 8; i++) {
        int r = r0 + ty * 8 + i;
        float* crow = Cp + (size_t)r * D_ + d0 + tx * 8;
        *reinterpret_cast<float4*>(crow)     = make_float4(acc[i][0], acc[i][1], acc[i][2], acc[i][3]);
        *reinterpret_cast<float4*>(crow + 4) = make_float4(acc[i][4], acc[i][5], acc[i][6], acc[i][7]);
    }
}

// ---------------------------------------------------------------------------
// Transpose: St[b, m, n] = S[b, n, m]   (32x32 smem tiles, coalesced both ways)
// ---------------------------------------------------------------------------
__global__ __launch_bounds__(256)
void transpose_kernel(const float* __restrict__ S, float* __restrict__ St)
{
    __shared__ float t[32][33];
    const int b  = blockIdx.z;
    const int n0 = blockIdx.y * 32;
    const int m0 = blockIdx.x * 32;
    const float* Sp  = S  + (size_t)b * N_ * M_;
    float*       Stp = St + (size_t)b * N_ * M_;

    const int x = threadIdx.x;   // 0..31
    const int y = threadIdx.y;   // 0..7
#pragma unroll
    for (int j = 0; j < 32; j += 8)
        t[y + j][x] = Sp[(size_t)(n0 + y + j) * M_ + m0 + x];
    __syncthreads();
#pragma unroll
    for (int j = 0; j < 32; j += 8)
        Stp[(size_t)(m0 + y + j) * N_ + n0 + x] = t[x][y + j];
}

// ---------------------------------------------------------------------------
// Masked row softmax, in place. rows = B*512, row length 512.
// mask indexed by column within batch (mask[b*512 + col]); mask==0 -> -inf.
// ---------------------------------------------------------------------------
__global__ __launch_bounds__(256)
void softmax_kernel(float* __restrict__ data, const int* __restrict__ mask)
{
    const int row = blockIdx.x;        // 0 .. B*512-1
    const int b   = row >> 9;
    float* d      = data + (size_t)row * 512;
    const int* mk = mask + (size_t)b * 512;

    const int t = threadIdx.x;
    __shared__ float red[256];

    const int m0 = mk[t];
    const int m1 = mk[t + 256];
    const float v0 = m0 ? d[t]       : -INFINITY;
    const float v1 = m1 ? d[t + 256] : -INFINITY;

    // max reduce
    red[t] = fmaxf(v0, v1);
    __syncthreads();
#pragma unroll
    for (int s = 128; s > 0; s >>= 1) {
        if (t < s) red[t] = fmaxf(red[t], red[t + s]);
        __syncthreads();
    }
    const float mx = red[0];
    __syncthreads();

    const float e0 = m0 ? expf(v0 - mx) : 0.f;
    const float e1 = m1 ? expf(v1 - mx) : 0.f;

    // sum reduce
    red[t] = e0 + e1;
    __syncthreads();
#pragma unroll
    for (int s = 128; s > 0; s >>= 1) {
        if (t < s) red[t] += red[t + s];
        __syncthreads();
    }
    const float inv = 1.f / red[0];

    d[t]       = e0 * inv;
    d[t + 256] = e1 * inv;
}

// ---------------------------------------------------------------------------
extern "C" void kernel_launch(void* const* d_in, const int* in_sizes, int n_in,
                              void* d_out, int out_size)
{
    const float* x1    = (const float*)d_in[0];   // [B, N, D]
    const float* x2    = (const float*)d_in[1];   // [B, M, D]
    const int*   mask1 = (const int*)  d_in[2];   // [B, N]
    const int*   mask2 = (const int*)  d_in[3];   // [B, M]

    float* out      = (float*)d_out;
    float* x1_coef  = out;                              // [B, N, D]
    float* x2_coef  = out + (size_t)B_ * N_ * D_;       // [B, M, D]

    float *S, *St;
    cudaGetSymbolAddress((void**)&S,  g_S);
    cudaGetSymbolAddress((void**)&St, g_St);

    // 1) align12 = x1 @ x2^T
    {
        dim3 g(M_ / 128, N_ / 128, B_);
        gemm_nt_kernel<<<g, 256>>>(x1, x2, S);
    }
    // 2) St = transpose(S)
    {
        dim3 g(M_ / 32, N_ / 32, B_);
        transpose_kernel<<<g, dim3(32, 8)>>>(S, St);
    }
    // 3) P12 = masked_softmax(S, mask2)   (rows over n, cols over m)
    softmax_kernel<<<B_ * N_, 256>>>(S, mask2);
    // 4) P21 = masked_softmax(St, mask1)  (rows over m, cols over n)
    softmax_kernel<<<B_ * M_, 256>>>(St, mask1);
    // 5) x1_coef = P12 @ x2
    {
        dim3 g(D_ / 128, N_ / 128, B_);
        gemm_nn_kernel<<<g, 256>>>(S, x2, x1_coef);
    }
    // 6) x2_coef = P21 @ x1
    {
        dim3 g(D_ / 128, M_ / 128, B_);
        gemm_nn_kernel<<<g, 256>>>(St, x1, x2_coef);
    }
}

// round 3
// speedup vs baseline: 2.2573x; 2.2573x over previous
#include <cuda_runtime.h>
#include <cuda_fp16.h>
#include <math.h>
#include <stdint.h>

#define B_  32
#define N_  512
#define M_  512
#define D_  1024

// ---------------------------------------------------------------------------
// Scratch (__device__ globals — allocation-free rule)
// ---------------------------------------------------------------------------
__device__ __align__(256) float  g_S  [(size_t)B_ * N_ * M_];
__device__ __align__(256) float  g_St [(size_t)B_ * N_ * M_];
__device__ __align__(256) __half g_x1h[(size_t)B_ * N_ * D_], g_x1l[(size_t)B_ * N_ * D_];
__device__ __align__(256) __half g_x2h[(size_t)B_ * M_ * D_], g_x2l[(size_t)B_ * M_ * D_];
__device__ __align__(256) __half g_x1th[(size_t)B_ * N_ * D_], g_x1tl[(size_t)B_ * N_ * D_];
__device__ __align__(256) __half g_x2th[(size_t)B_ * M_ * D_], g_x2tl[(size_t)B_ * M_ * D_];
__device__ __align__(256) __half g_p12h[(size_t)B_ * N_ * M_], g_p12l[(size_t)B_ * N_ * M_];
__device__ __align__(256) __half g_p21h[(size_t)B_ * N_ * M_], g_p21l[(size_t)B_ * N_ * M_];

// ---------------------------------------------------------------------------
// helpers (all plain sm_80+ features — valid on sm_103 non-'a' target)
// ---------------------------------------------------------------------------
__device__ __forceinline__ uint32_t smem_u32(const void* p) {
    uint32_t a;
    asm("{ .reg .u64 t; cvta.to.shared.u64 t, %1; cvt.u32.u64 %0, t; }" : "=r"(a) : "l"(p));
    return a;
}
__device__ __forceinline__ void cp16(uint32_t dst, const void* gsrc) {
    asm volatile("cp.async.cg.shared.global [%0], [%1], 16;" :: "r"(dst), "l"(gsrc) : "memory");
}
__device__ __forceinline__ void cp_commit() { asm volatile("cp.async.commit_group;" ::: "memory"); }
template <int NW> __device__ __forceinline__ void cp_wait() {
    asm volatile("cp.async.wait_group %0;" :: "n"(NW) : "memory");
}
__device__ __forceinline__ void ldsm4(uint32_t* r, uint32_t addr) {
    asm volatile("ldmatrix.sync.aligned.m8n8.x4.shared.b16 {%0,%1,%2,%3}, [%4];"
                 : "=r"(r[0]), "=r"(r[1]), "=r"(r[2]), "=r"(r[3]) : "r"(addr));
}
__device__ __forceinline__ void mma16816(float* c, const uint32_t* a, uint32_t b0, uint32_t b1) {
    asm volatile(
        "mma.sync.aligned.m16n8k16.row.col.f32.f16.f16.f32 "
        "{%0,%1,%2,%3}, {%4,%5,%6,%7}, {%8,%9}, {%0,%1,%2,%3};"
        : "+f"(c[0]), "+f"(c[1]), "+f"(c[2]), "+f"(c[3])
        : "r"(a[0]), "r"(a[1]), "r"(a[2]), "r"(a[3]), "r"(b0), "r"(b1));
}

// SW64-swizzled tile address: rows of 64B (32 halves), 16B chunks permuted per row pair
__device__ __forceinline__ uint32_t tadr(uint32_t tbase, int row, int chunk) {
    return tbase + row * 64 + ((chunk ^ ((row >> 1) & 3)) << 4);
}

// ---------------------------------------------------------------------------
// HMMA GEMM: C[rA, rB] = sum_k (Ahi+Alo)[rA,k] * (Bhi+Blo)[rB,k]   (both K-major)
// CTA 128x128, 8 warps (warp tile 64x32), K-step 32, double-buffered cp.async.
// ---------------------------------------------------------------------------
#define TILE_A_H 0
#define TILE_A_L 8192
#define TILE_B_H 16384
#define TILE_B_L 24576
#define STAGE_SZ 32768
#define GEMM_SMEM (2 * STAGE_SZ)

__device__ __forceinline__ void load_stage(
    uint32_t sbase, int tid,
    const __half* __restrict__ Ahp, const __half* __restrict__ Alp,
    const __half* __restrict__ Bhp, const __half* __restrict__ Blp,
    int Kt, int k0)
{
#pragma unroll
    for (int i = 0; i < 2; i++) {
        const int idx  = tid + i * 256;      // 0..511
        const int row  = idx >> 2;           // 0..127
        const int c    = idx & 3;            // 16B chunk
        const uint32_t sw = (uint32_t)(row * 64 + ((c ^ ((row >> 1) & 3)) << 4));
        const size_t g = (size_t)row * Kt + k0 + c * 8;
        cp16(sbase + TILE_A_H + sw, Ahp + g);
        cp16(sbase + TILE_A_L + sw, Alp + g);
        cp16(sbase + TILE_B_H + sw, Bhp + g);
        cp16(sbase + TILE_B_L + sw, Blp + g);
    }
    cp_commit();
}

__global__ __launch_bounds__(256)
void gemm_hmma(const __half* __restrict__ Ah, const __half* __restrict__ Al,
               const __half* __restrict__ Bh, const __half* __restrict__ Bl,
               float* __restrict__ C,
               int Kt, long long aB, long long bB, long long cB, int ldc)
{
    extern __shared__ __align__(128) char smem[];
    const uint32_t sb = smem_u32(smem);
    const int tid  = threadIdx.x;
    const int warp = tid >> 5;
    const int lane = tid & 31;
    const int b    = blockIdx.z;
    const int rA0  = blockIdx.y * 128;
    const int rB0  = blockIdx.x * 128;

    const __half* Ahp = Ah + (size_t)b * aB + (size_t)rA0 * Kt;
    const __half* Alp = Al + (size_t)b * aB + (size_t)rA0 * Kt;
    const __half* Bhp = Bh + (size_t)b * bB + (size_t)rB0 * Kt;
    const __half* Blp = Bl + (size_t)b * bB + (size_t)rB0 * Kt;

    const int warp_m = (warp >> 2) << 6;    // 0 or 64
    const int warp_n = (warp & 3) << 5;     // 0,32,64,96

    float acc[4][4][4];
#pragma unroll
    for (int i = 0; i < 4; i++)
#pragma unroll
        for (int j = 0; j < 4; j++)
#pragma unroll
            for (int q = 0; q < 4; q++) acc[i][j][q] = 0.f;

    // ldmatrix per-lane row/chunk components
    const int arow = lane & 15;                      // A: m offset within 16
    const int acx  = (lane >> 4) & 1;                // A: k16-half chunk
    const int brow = (lane & 7) + ((lane & 16) >> 1);// B: n offset within 16
    const int bcx  = (lane >> 3) & 1;                // B: k16-half chunk

    const int T = Kt >> 5;   // K-steps of 32
    load_stage(sb, tid, Ahp, Alp, Bhp, Blp, Kt, 0);

    for (int t = 0; t < T; t++) {
        if (t + 1 < T) {
            load_stage(sb + (uint32_t)((t + 1) & 1) * STAGE_SZ, tid,
                       Ahp, Alp, Bhp, Blp, Kt, (t + 1) << 5);
            cp_wait<1>();
        } else {
            cp_wait<0>();
        }
        __syncthreads();

        const uint32_t st = sb + (uint32_t)(t & 1) * STAGE_SZ;
#pragma unroll
        for (int kk = 0; kk < 2; kk++) {
            uint32_t AH[4][4], AL[4][4], BH[2][4], BL[2][4];
            const int ac = kk * 2 + acx;
            const int bc = kk * 2 + bcx;
#pragma unroll
            for (int i = 0; i < 4; i++) {
                ldsm4(AH[i], tadr(st + TILE_A_H, warp_m + i * 16 + arow, ac));
                ldsm4(AL[i], tadr(st + TILE_A_L, warp_m + i * 16 + arow, ac));
            }
#pragma unroll
            for (int j = 0; j < 2; j++) {
                ldsm4(BH[j], tadr(st + TILE_B_H, warp_n + j * 16 + brow, bc));
                ldsm4(BL[j], tadr(st + TILE_B_L, warp_n + j * 16 + brow, bc));
            }
#pragma unroll
            for (int i = 0; i < 4; i++)
#pragma unroll
                for (int j = 0; j < 4; j++) {
                    const uint32_t bh0 = BH[j >> 1][(j & 1) * 2];
                    const uint32_t bh1 = BH[j >> 1][(j & 1) * 2 + 1];
                    const uint32_t bl0 = BL[j >> 1][(j & 1) * 2];
                    const uint32_t bl1 = BL[j >> 1][(j & 1) * 2 + 1];
                    mma16816(acc[i][j], AH[i], bh0, bh1);   // hi*hi
                    mma16816(acc[i][j], AH[i], bl0, bl1);   // hi*lo
                    mma16816(acc[i][j], AL[i], bh0, bh1);   // lo*hi
                }
        }
        __syncthreads();
    }

    // epilogue: direct f32 stores
    float* Cb = C + (size_t)b * cB;
    const int tr = lane >> 2;          // 0..7
    const int tc = (lane & 3) * 2;     // 0,2,4,6
#pragma unroll
    for (int i = 0; i < 4; i++) {
#pragma unroll
        for (int j = 0; j < 4; j++) {
            const int row = rA0 + warp_m + i * 16 + tr;
            const int col = rB0 + warp_n + j * 8 + tc;
            *reinterpret_cast<float2*>(Cb + (size_t)row * ldc + col) =
                make_float2(acc[i][j][0], acc[i][j][1]);
            *reinterpret_cast<float2*>(Cb + (size_t)(row + 8) * ldc + col) =
                make_float2(acc[i][j][2], acc[i][j][3]);
        }
    }
}

// ---------------------------------------------------------------------------
// fp32 -> fp16 hi/lo split, straight + transposed copies
// ---------------------------------------------------------------------------
__global__ __launch_bounds__(256)
void conv_split(const float* __restrict__ x,
                __half* __restrict__ xh,  __half* __restrict__ xl,
                __half* __restrict__ xth, __half* __restrict__ xtl,
                int R, int D)
{
    __shared__ float t[32][33];
    const int b  = blockIdx.z;
    const int r0 = blockIdx.y * 32;
    const int d0 = blockIdx.x * 32;
    const int tx = threadIdx.x, ty = threadIdx.y;
    const size_t bbase = (size_t)b * R * D;

#pragma unroll
    for (int j = 0; j < 32; j += 8) {
        const int r = r0 + ty + j;
        const float v = x[bbase + (size_t)r * D + d0 + tx];
        const __half h = __float2half_rn(v);
        const __half l = __float2half_rn(v - __half2float(h));
        const size_t idx = bbase + (size_t)r * D + d0 + tx;
        xh[idx] = h;  xl[idx] = l;
        t[ty + j][tx] = v;
    }
    __syncthreads();
#pragma unroll
    for (int j = 0; j < 32; j += 8) {
        const int d = d0 + ty + j;
        const int r = r0 + tx;
        const float v = t[tx][ty + j];
        const __half h = __float2half_rn(v);
        const __half l = __float2half_rn(v - __half2float(h));
        const size_t idx = bbase + (size_t)d * R + r;
        xth[idx] = h;  xtl[idx] = l;
    }
}

// ---------------------------------------------------------------------------
// Transpose: St[b, m, n] = S[b, n, m]
// ---------------------------------------------------------------------------
__global__ __launch_bounds__(256)
void transpose_kernel(const float* __restrict__ S, float* __restrict__ St)
{
    __shared__ float t[32][33];
    const int b  = blockIdx.z;
    const int n0 = blockIdx.y * 32;
    const int m0 = blockIdx.x * 32;
    const float* Sp  = S  + (size_t)b * N_ * M_;
    float*       Stp = St + (size_t)b * N_ * M_;
    const int x = threadIdx.x, y = threadIdx.y;
#pragma unroll
    for (int j = 0; j < 32; j += 8)
        t[y + j][x] = Sp[(size_t)(n0 + y + j) * M_ + m0 + x];
    __syncthreads();
#pragma unroll
    for (int j = 0; j < 32; j += 8)
        Stp[(size_t)(m0 + y + j) * N_ + n0 + x] = t[x][y + j];
}

// ---------------------------------------------------------------------------
// Masked row softmax -> fp16 hi/lo probability pair
// ---------------------------------------------------------------------------
__global__ __launch_bounds__(256)
void softmax_kernel(const float* __restrict__ data, const int* __restrict__ mask,
                    __half* __restrict__ ph, __half* __restrict__ pl)
{
    const int row = blockIdx.x;
    const int b   = row >> 9;
    const float* d = data + (size_t)row * 512;
    const int*  mk = mask + (size_t)b * 512;
    const int t = threadIdx.x;
    __shared__ float red[256];

    const int m0 = mk[t];
    const int m1 = mk[t + 256];
    const float v0 = m0 ? d[t]       : -INFINITY;
    const float v1 = m1 ? d[t + 256] : -INFINITY;

    red[t] = fmaxf(v0, v1);
    __syncthreads();
#pragma unroll
    for (int s = 128; s > 0; s >>= 1) {
        if (t < s) red[t] = fmaxf(red[t], red[t + s]);
        __syncthreads();
    }
    const float mx = red[0];
    __syncthreads();

    const float e0 = m0 ? __expf(v0 - mx) : 0.f;
    const float e1 = m1 ? __expf(v1 - mx) : 0.f;

    red[t] = e0 + e1;
    __syncthreads();
#pragma unroll
    for (int s = 128; s > 0; s >>= 1) {
        if (t < s) red[t] += red[t + s];
        __syncthreads();
    }
    const float inv = 1.f / red[0];

    const float p0 = e0 * inv, p1 = e1 * inv;
    const __half h0 = __float2half_rn(p0);
    const __half h1 = __float2half_rn(p1);
    const size_t o = (size_t)row * 512;
    ph[o + t]       = h0;
    pl[o + t]       = __float2half_rn(p0 - __half2float(h0));
    ph[o + t + 256] = h1;
    pl[o + t + 256] = __float2half_rn(p1 - __half2float(h1));
}

// ---------------------------------------------------------------------------
extern "C" void kernel_launch(void* const* d_in, const int* in_sizes, int n_in,
                              void* d_out, int out_size)
{
    const float* x1    = (const float*)d_in[0];
    const float* x2    = (const float*)d_in[1];
    const int*   mask1 = (const int*)  d_in[2];
    const int*   mask2 = (const int*)  d_in[3];

    float* out     = (float*)d_out;
    float* x1_coef = out;
    float* x2_coef = out + (size_t)B_ * N_ * D_;

    float *S, *St;
    __half *x1h, *x1l, *x2h, *x2l, *x1th, *x1tl, *x2th, *x2tl;
    __half *p12h, *p12l, *p21h, *p21l;
    cudaGetSymbolAddress((void**)&S,    g_S);
    cudaGetSymbolAddress((void**)&St,   g_St);
    cudaGetSymbolAddress((void**)&x1h,  g_x1h);   cudaGetSymbolAddress((void**)&x1l,  g_x1l);
    cudaGetSymbolAddress((void**)&x2h,  g_x2h);   cudaGetSymbolAddress((void**)&x2l,  g_x2l);
    cudaGetSymbolAddress((void**)&x1th, g_x1th);  cudaGetSymbolAddress((void**)&x1tl, g_x1tl);
    cudaGetSymbolAddress((void**)&x2th, g_x2th);  cudaGetSymbolAddress((void**)&x2tl, g_x2tl);
    cudaGetSymbolAddress((void**)&p12h, g_p12h);  cudaGetSymbolAddress((void**)&p12l, g_p12l);
    cudaGetSymbolAddress((void**)&p21h, g_p21h);  cudaGetSymbolAddress((void**)&p21l, g_p21l);

    cudaFuncSetAttribute(gemm_hmma, cudaFuncAttributeMaxDynamicSharedMemorySize, GEMM_SMEM);

    const dim3 cb(32, 8);
    // 1) split + transpose conversions
    conv_split<<<dim3(D_ / 32, N_ / 32, B_), cb>>>(x1, x1h, x1l, x1th, x1tl, N_, D_);
    conv_split<<<dim3(D_ / 32, M_ / 32, B_), cb>>>(x2, x2h, x2l, x2th, x2tl, M_, D_);
    // 2) align12 = x1 @ x2^T   (A rows n, B rows m, K = D)
    gemm_hmma<<<dim3(M_ / 128, N_ / 128, B_), 256, GEMM_SMEM>>>(
        x1h, x1l, x2h, x2l, S, D_,
        (long long)N_ * D_, (long long)M_ * D_, (long long)N_ * M_, M_);
    // 3) St = S^T
    transpose_kernel<<<dim3(M_ / 32, N_ / 32, B_), cb>>>(S, St);
    // 4) softmaxes -> fp16 hi/lo
    softmax_kernel<<<B_ * N_, 256>>>(S,  mask2, p12h, p12l);
    softmax_kernel<<<B_ * M_, 256>>>(St, mask1, p21h, p21l);
    // 5) x1_coef = P12 @ x2   (A rows n, K = m, B rows = d via x2^T copy)
    gemm_hmma<<<dim3(D_ / 128, N_ / 128, B_), 256, GEMM_SMEM>>>(
        p12h, p12l, x2th, x2tl, x1_coef, M_,
        (long long)N_ * M_, (long long)D_ * M_, (long long)N_ * D_, D_);
    // 6) x2_coef = P21 @ x1
    gemm_hmma<<<dim3(D_ / 128, M_ / 128, B_), 256, GEMM_SMEM>>>(
        p21h, p21l, x1th, x1tl, x2_coef, N_,
        (long long)M_ * N_, (long long)D_ * N_, (long long)M_ * D_, D_);
}

// round 4
// speedup vs baseline: 3.5942x; 1.5923x over previous
#include <cuda_runtime.h>
#include <cuda_fp16.h>
#include <math.h>
#include <stdint.h>

#define B_  32
#define N_  512
#define M_  512
#define D_  1024

// ---------------------------------------------------------------------------
// Scratch (__device__ globals — allocation-free rule)
// ---------------------------------------------------------------------------
__device__ __align__(256) float  g_S  [(size_t)B_ * N_ * M_];   // align12 -> P12 in place
__device__ __align__(256) float  g_P21[(size_t)B_ * N_ * M_];   // P21 [m, n]
__device__ __align__(256) __half g_x1h[(size_t)B_ * N_ * D_], g_x1l[(size_t)B_ * N_ * D_];
__device__ __align__(256) __half g_x2h[(size_t)B_ * M_ * D_], g_x2l[(size_t)B_ * M_ * D_];

// ---------------------------------------------------------------------------
// helpers (plain sm_80+ features — valid on sm_103 non-'a' target)
// ---------------------------------------------------------------------------
__device__ __forceinline__ uint32_t smem_u32(const void* p) {
    uint32_t a;
    asm("{ .reg .u64 t; cvta.to.shared.u64 t, %1; cvt.u32.u64 %0, t; }" : "=r"(a) : "l"(p));
    return a;
}
__device__ __forceinline__ void cp16(uint32_t dst, const void* gsrc) {
    asm volatile("cp.async.cg.shared.global [%0], [%1], 16;" :: "r"(dst), "l"(gsrc) : "memory");
}
__device__ __forceinline__ void cp_commit() { asm volatile("cp.async.commit_group;" ::: "memory"); }
template <int NW> __device__ __forceinline__ void cp_wait() {
    asm volatile("cp.async.wait_group %0;" :: "n"(NW) : "memory");
}
__device__ __forceinline__ void ldsm4(uint32_t* r, uint32_t addr) {
    asm volatile("ldmatrix.sync.aligned.m8n8.x4.shared.b16 {%0,%1,%2,%3}, [%4];"
                 : "=r"(r[0]), "=r"(r[1]), "=r"(r[2]), "=r"(r[3]) : "r"(addr));
}
__device__ __forceinline__ void mma16816(float* c, const uint32_t* a, uint32_t b0, uint32_t b1) {
    asm volatile(
        "mma.sync.aligned.m16n8k16.row.col.f32.f16.f16.f32 "
        "{%0,%1,%2,%3}, {%4,%5,%6,%7}, {%8,%9}, {%0,%1,%2,%3};"
        : "+f"(c[0]), "+f"(c[1]), "+f"(c[2]), "+f"(c[3])
        : "r"(a[0]), "r"(a[1]), "r"(a[2]), "r"(a[3]), "r"(b0), "r"(b1));
}

// SW64-swizzled tile address: rows of 64B (32 halves), 16B chunks permuted per row pair
__device__ __forceinline__ uint32_t tadr(uint32_t tbase, int row, int chunk) {
    return tbase + row * 64 + ((chunk ^ ((row >> 1) & 3)) << 4);
}

// ---------------------------------------------------------------------------
// HMMA GEMM (NT): C[rA, rB] = sum_k (Ahi+Alo)[rA,k] * (Bhi+Blo)[rB,k]
// CTA 128x128, 8 warps (warp tile 64x32), K-step 32, double-buffered cp.async.
// (unchanged from round 3 — proven correct)
// ---------------------------------------------------------------------------
#define TILE_A_H 0
#define TILE_A_L 8192
#define TILE_B_H 16384
#define TILE_B_L 24576
#define STAGE_SZ 32768
#define GEMM_SMEM (2 * STAGE_SZ)

__device__ __forceinline__ void load_stage(
    uint32_t sbase, int tid,
    const __half* __restrict__ Ahp, const __half* __restrict__ Alp,
    const __half* __restrict__ Bhp, const __half* __restrict__ Blp,
    int Kt, int k0)
{
#pragma unroll
    for (int i = 0; i < 2; i++) {
        const int idx  = tid + i * 256;      // 0..511
        const int row  = idx >> 2;           // 0..127
        const int c    = idx & 3;            // 16B chunk
        const uint32_t sw = (uint32_t)(row * 64 + ((c ^ ((row >> 1) & 3)) << 4));
        const size_t g = (size_t)row * Kt + k0 + c * 8;
        cp16(sbase + TILE_A_H + sw, Ahp + g);
        cp16(sbase + TILE_A_L + sw, Alp + g);
        cp16(sbase + TILE_B_H + sw, Bhp + g);
        cp16(sbase + TILE_B_L + sw, Blp + g);
    }
    cp_commit();
}

__global__ __launch_bounds__(256)
void gemm_hmma(const __half* __restrict__ Ah, const __half* __restrict__ Al,
               const __half* __restrict__ Bh, const __half* __restrict__ Bl,
               float* __restrict__ C,
               int Kt, long long aB, long long bB, long long cB, int ldc)
{
    extern __shared__ __align__(128) char smem[];
    const uint32_t sb = smem_u32(smem);
    const int tid  = threadIdx.x;
    const int warp = tid >> 5;
    const int lane = tid & 31;
    const int b    = blockIdx.z;
    const int rA0  = blockIdx.y * 128;
    const int rB0  = blockIdx.x * 128;

    const __half* Ahp = Ah + (size_t)b * aB + (size_t)rA0 * Kt;
    const __half* Alp = Al + (size_t)b * aB + (size_t)rA0 * Kt;
    const __half* Bhp = Bh + (size_t)b * bB + (size_t)rB0 * Kt;
    const __half* Blp = Bl + (size_t)b * bB + (size_t)rB0 * Kt;

    const int warp_m = (warp >> 2) << 6;    // 0 or 64
    const int warp_n = (warp & 3) << 5;     // 0,32,64,96

    float acc[4][4][4];
#pragma unroll
    for (int i = 0; i < 4; i++)
#pragma unroll
        for (int j = 0; j < 4; j++)
#pragma unroll
            for (int q = 0; q < 4; q++) acc[i][j][q] = 0.f;

    const int arow = lane & 15;
    const int acx  = (lane >> 4) & 1;
    const int brow = (lane & 7) + ((lane & 16) >> 1);
    const int bcx  = (lane >> 3) & 1;

    const int T = Kt >> 5;
    load_stage(sb, tid, Ahp, Alp, Bhp, Blp, Kt, 0);

    for (int t = 0; t < T; t++) {
        if (t + 1 < T) {
            load_stage(sb + (uint32_t)((t + 1) & 1) * STAGE_SZ, tid,
                       Ahp, Alp, Bhp, Blp, Kt, (t + 1) << 5);
            cp_wait<1>();
        } else {
            cp_wait<0>();
        }
        __syncthreads();

        const uint32_t st = sb + (uint32_t)(t & 1) * STAGE_SZ;
#pragma unroll
        for (int kk = 0; kk < 2; kk++) {
            uint32_t AH[4][4], AL[4][4], BH[2][4], BL[2][4];
            const int ac = kk * 2 + acx;
            const int bc = kk * 2 + bcx;
#pragma unroll
            for (int i = 0; i < 4; i++) {
                ldsm4(AH[i], tadr(st + TILE_A_H, warp_m + i * 16 + arow, ac));
                ldsm4(AL[i], tadr(st + TILE_A_L, warp_m + i * 16 + arow, ac));
            }
#pragma unroll
            for (int j = 0; j < 2; j++) {
                ldsm4(BH[j], tadr(st + TILE_B_H, warp_n + j * 16 + brow, bc));
                ldsm4(BL[j], tadr(st + TILE_B_L, warp_n + j * 16 + brow, bc));
            }
#pragma unroll
            for (int i = 0; i < 4; i++)
#pragma unroll
                for (int j = 0; j < 4; j++) {
                    const uint32_t bh0 = BH[j >> 1][(j & 1) * 2];
                    const uint32_t bh1 = BH[j >> 1][(j & 1) * 2 + 1];
                    const uint32_t bl0 = BL[j >> 1][(j & 1) * 2];
                    const uint32_t bl1 = BL[j >> 1][(j & 1) * 2 + 1];
                    mma16816(acc[i][j], AH[i], bh0, bh1);   // hi*hi
                    mma16816(acc[i][j], AH[i], bl0, bl1);   // hi*lo
                    mma16816(acc[i][j], AL[i], bh0, bh1);   // lo*hi
                }
        }
        __syncthreads();
    }

    float* Cb = C + (size_t)b * cB;
    const int tr = lane >> 2;
    const int tc = (lane & 3) * 2;
#pragma unroll
    for (int i = 0; i < 4; i++) {
#pragma unroll
        for (int j = 0; j < 4; j++) {
            const int row = rA0 + warp_m + i * 16 + tr;
            const int col = rB0 + warp_n + j * 8 + tc;
            *reinterpret_cast<float2*>(Cb + (size_t)row * ldc + col) =
                make_float2(acc[i][j][0], acc[i][j][1]);
            *reinterpret_cast<float2*>(Cb + (size_t)(row + 8) * ldc + col) =
                make_float2(acc[i][j][2], acc[i][j][3]);
        }
    }
}

// ---------------------------------------------------------------------------
// fp32 -> fp16 hi/lo split (straight only), vectorized grid-stride
// ---------------------------------------------------------------------------
__global__ __launch_bounds__(256)
void split_kernel(const float* __restrict__ x,
                  __half* __restrict__ xh, __half* __restrict__ xl, int n4)
{
    const int stride = gridDim.x * blockDim.x;
    for (int i = blockIdx.x * blockDim.x + threadIdx.x; i < n4; i += stride) {
        const float4 v = reinterpret_cast<const float4*>(x)[i];
        const __half h0 = __float2half_rn(v.x), h1 = __float2half_rn(v.y);
        const __half h2 = __float2half_rn(v.z), h3 = __float2half_rn(v.w);
        const __half l0 = __float2half_rn(v.x - __half2float(h0));
        const __half l1 = __float2half_rn(v.y - __half2float(h1));
        const __half l2 = __float2half_rn(v.z - __half2float(h2));
        const __half l3 = __float2half_rn(v.w - __half2float(h3));
        __half2* hp = reinterpret_cast<__half2*>(xh) + i * 2;
        __half2* lp = reinterpret_cast<__half2*>(xl) + i * 2;
        hp[0] = __halves2half2(h0, h1);  hp[1] = __halves2half2(h2, h3);
        lp[0] = __halves2half2(l0, l1);  lp[1] = __halves2half2(l2, l3);
    }
}

// ---------------------------------------------------------------------------
// Row softmax in place (fp32): P[row, :] = softmax(S[row, :] with mask over cols)
// ---------------------------------------------------------------------------
__global__ __launch_bounds__(256)
void softmax_row(float* __restrict__ data, const int* __restrict__ mask)
{
    const int row = blockIdx.x;
    const int b   = row >> 9;
    float* d      = data + (size_t)row * 512;
    const int* mk = mask + (size_t)b * 512;
    const int t = threadIdx.x;
    __shared__ float red[256];

    const int m0 = mk[t];
    const int m1 = mk[t + 256];
    const float v0 = m0 ? d[t]       : -INFINITY;
    const float v1 = m1 ? d[t + 256] : -INFINITY;

    red[t] = fmaxf(v0, v1);
    __syncthreads();
#pragma unroll
    for (int s = 128; s > 0; s >>= 1) {
        if (t < s) red[t] = fmaxf(red[t], red[t + s]);
        __syncthreads();
    }
    const float mx = red[0];
    __syncthreads();

    const float e0 = m0 ? __expf(v0 - mx) : 0.f;
    const float e1 = m1 ? __expf(v1 - mx) : 0.f;

    red[t] = e0 + e1;
    __syncthreads();
#pragma unroll
    for (int s = 128; s > 0; s >>= 1) {
        if (t < s) red[t] += red[t + s];
        __syncthreads();
    }
    const float inv = 1.f / red[0];

    d[t]       = e0 * inv;
    d[t + 256] = e1 * inv;
}

// ---------------------------------------------------------------------------
// Column softmax: P21[b, m, n] = softmax_n( S[b, n, m] masked by mask1[b, n] )
// Block handles (b, 32 m-columns); full column slab in smem.
// ---------------------------------------------------------------------------
#define COLSM_SMEM (512 * 33 * 4)

__global__ __launch_bounds__(256)
void softmax_col(const float* __restrict__ S, const int* __restrict__ mask,
                 float* __restrict__ P21)
{
    extern __shared__ float slab[];            // [512][33]
    __shared__ float red[8][32];
    __shared__ float maxs[32], invs[32];

    const int b  = blockIdx.y;
    const int m0 = blockIdx.x * 32;
    const int t  = threadIdx.x;
    const float* Sp  = S   + (size_t)b * N_ * M_;
    const int*   mk  = mask + (size_t)b * 512;
    float*       Pp  = P21 + (size_t)b * N_ * M_;

    // load masked slab: slab[n][m]
    for (int idx = t; idx < 512 * 32; idx += 256) {
        const int n = idx >> 5, m = idx & 31;
        const float v = mk[n] ? Sp[(size_t)n * M_ + m0 + m] : -INFINITY;
        slab[n * 33 + m] = v;
    }
    __syncthreads();

    const int m = t & 31, r = t >> 5;
    float lmax = -INFINITY;
    for (int n = r; n < 512; n += 8) lmax = fmaxf(lmax, slab[n * 33 + m]);
    red[r][m] = lmax;
    __syncthreads();
    if (t < 32) {
        float mx = red[0][t];
#pragma unroll
        for (int k = 1; k < 8; k++) mx = fmaxf(mx, red[k][t]);
        maxs[t] = mx;
    }
    __syncthreads();

    float lsum = 0.f;
    const float mx = maxs[m];
    for (int n = r; n < 512; n += 8) {
        const float e = __expf(slab[n * 33 + m] - mx);
        slab[n * 33 + m] = e;
        lsum += e;
    }
    red[r][m] = lsum;
    __syncthreads();
    if (t < 32) {
        float s = red[0][t];
#pragma unroll
        for (int k = 1; k < 8; k++) s += red[k][t];
        invs[t] = 1.f / s;
    }
    __syncthreads();

    // write P21[m0+m, n], coalesced over n
    for (int idx = t; idx < 32 * 512; idx += 256) {
        const int mm = idx >> 9, n = idx & 511;
        Pp[(size_t)(m0 + mm) * 512 + n] = slab[n * 33 + mm] * invs[mm];
    }
}

// ---------------------------------------------------------------------------
// Sparse apply: out[row, :] = sum_{k: P[row,k] > TAU} P[row,k] * X[k, :]
// Softmax of sigma=32 logits is near-one-hot: typically 3-6 significant terms.
// Deterministic list build via warp-ballot prefix (no atomics).
// ---------------------------------------------------------------------------
#define TAU 1e-7f

__global__ __launch_bounds__(256)
void sparse_apply(const float* __restrict__ P, const float* __restrict__ X,
                  float* __restrict__ out)
{
    __shared__ float sp[512];
    __shared__ int   sm[512];
    __shared__ int   scnt;

    const int row = blockIdx.x;           // 0 .. B*512-1
    const int b   = row >> 9;
    const float* Pr = P + (size_t)row * 512;
    const float* Xb = X + (size_t)b * 512 * D_;
    const int t = threadIdx.x;

    if (t < 32) {
        int base = 0;
#pragma unroll
        for (int j = 0; j < 16; j++) {
            const float p = Pr[j * 32 + t];
            const bool sig = p > TAU;
            const unsigned mask = __ballot_sync(0xffffffffu, sig);
            if (sig) {
                const int pos = base + __popc(mask & ((1u << t) - 1u));
                sm[pos] = j * 32 + t;
                sp[pos] = p;
            }
            base += __popc(mask);
        }
        if (t == 0) scnt = base;
    }
    __syncthreads();

    const int cnt = scnt;
    float4 acc = make_float4(0.f, 0.f, 0.f, 0.f);
    for (int i = 0; i < cnt; i++) {
        const float p = sp[i];
        const float4 xv = *reinterpret_cast<const float4*>(Xb + (size_t)sm[i] * D_ + t * 4);
        acc.x += p * xv.x;  acc.y += p * xv.y;
        acc.z += p * xv.z;  acc.w += p * xv.w;
    }
    *reinterpret_cast<float4*>(out + (size_t)row * D_ + t * 4) = acc;
}

// ---------------------------------------------------------------------------
extern "C" void kernel_launch(void* const* d_in, const int* in_sizes, int n_in,
                              void* d_out, int out_size)
{
    const float* x1    = (const float*)d_in[0];
    const float* x2    = (const float*)d_in[1];
    const int*   mask1 = (const int*)  d_in[2];
    const int*   mask2 = (const int*)  d_in[3];

    float* out     = (float*)d_out;
    float* x1_coef = out;
    float* x2_coef = out + (size_t)B_ * N_ * D_;

    float *S, *P21;
    __half *x1h, *x1l, *x2h, *x2l;
    cudaGetSymbolAddress((void**)&S,   g_S);
    cudaGetSymbolAddress((void**)&P21, g_P21);
    cudaGetSymbolAddress((void**)&x1h, g_x1h);  cudaGetSymbolAddress((void**)&x1l, g_x1l);
    cudaGetSymbolAddress((void**)&x2h, g_x2h);  cudaGetSymbolAddress((void**)&x2l, g_x2l);

    cudaFuncSetAttribute(gemm_hmma,   cudaFuncAttributeMaxDynamicSharedMemorySize, GEMM_SMEM);
    cudaFuncSetAttribute(softmax_col, cudaFuncAttributeMaxDynamicSharedMemorySize, COLSM_SMEM);

    // 1) fp16 hi/lo splits (straight layout only)
    split_kernel<<<592, 256>>>(x1, x1h, x1l, B_ * N_ * D_ / 4);
    split_kernel<<<592, 256>>>(x2, x2h, x2l, B_ * M_ * D_ / 4);

    // 2) S = x1 @ x2^T  (fp16-split HMMA, fp32 result)
    gemm_hmma<<<dim3(M_ / 128, N_ / 128, B_), 256, GEMM_SMEM>>>(
        x1h, x1l, x2h, x2l, S, D_,
        (long long)N_ * D_, (long long)M_ * D_, (long long)N_ * M_, M_);

    // 3) P21[m, n] = softmax over n of S[n, m] (mask1) — reads raw S, so run first
    softmax_col<<<dim3(M_ / 32, B_), 256, COLSM_SMEM>>>(S, mask1, P21);

    // 4) P12 = softmax rows of S (mask2), in place
    softmax_row<<<B_ * N_, 256>>>(S, mask2);

    // 5) outputs via near-one-hot sparse apply (exact fp32 on original inputs)
    sparse_apply<<<B_ * N_, 256>>>(S,   x2, x1_coef);
    sparse_apply<<<B_ * M_, 256>>>(P21, x1, x2_coef);
}

// round 5
// speedup vs baseline: 4.4303x; 1.2326x over previous
#include <cuda_runtime.h>
#include <cuda_fp16.h>
#include <math.h>
#include <stdint.h>

#define B_  32
#define N_  512
#define M_  512
#define D_  1024

// ---------------------------------------------------------------------------
// Scratch (__device__ globals — allocation-free rule)
// ---------------------------------------------------------------------------
__device__ __align__(256) float  g_S  [(size_t)B_ * N_ * M_];   // raw logits [n, m]
__device__ __align__(256) float  g_St [(size_t)B_ * N_ * M_];   // raw logits [m, n]
__device__ __align__(256) __half g_x1h[(size_t)B_ * N_ * D_], g_x1l[(size_t)B_ * N_ * D_];
__device__ __align__(256) __half g_x2h[(size_t)B_ * M_ * D_], g_x2l[(size_t)B_ * M_ * D_];

// ---------------------------------------------------------------------------
// helpers (plain sm_80+ features — valid on sm_103 non-'a' target)
// ---------------------------------------------------------------------------
__device__ __forceinline__ uint32_t smem_u32(const void* p) {
    uint32_t a;
    asm("{ .reg .u64 t; cvta.to.shared.u64 t, %1; cvt.u32.u64 %0, t; }" : "=r"(a) : "l"(p));
    return a;
}
__device__ __forceinline__ void cp16(uint32_t dst, const void* gsrc) {
    asm volatile("cp.async.cg.shared.global [%0], [%1], 16;" :: "r"(dst), "l"(gsrc) : "memory");
}
__device__ __forceinline__ void cp_commit() { asm volatile("cp.async.commit_group;" ::: "memory"); }
template <int NW> __device__ __forceinline__ void cp_wait() {
    asm volatile("cp.async.wait_group %0;" :: "n"(NW) : "memory");
}
__device__ __forceinline__ void ldsm4(uint32_t* r, uint32_t addr) {
    asm volatile("ldmatrix.sync.aligned.m8n8.x4.shared.b16 {%0,%1,%2,%3}, [%4];"
                 : "=r"(r[0]), "=r"(r[1]), "=r"(r[2]), "=r"(r[3]) : "r"(addr));
}
__device__ __forceinline__ void mma16816(float* c, const uint32_t* a, uint32_t b0, uint32_t b1) {
    asm volatile(
        "mma.sync.aligned.m16n8k16.row.col.f32.f16.f16.f32 "
        "{%0,%1,%2,%3}, {%4,%5,%6,%7}, {%8,%9}, {%0,%1,%2,%3};"
        : "+f"(c[0]), "+f"(c[1]), "+f"(c[2]), "+f"(c[3])
        : "r"(a[0]), "r"(a[1]), "r"(a[2]), "r"(a[3]), "r"(b0), "r"(b1));
}
__device__ __forceinline__ uint32_t tadr(uint32_t tbase, int row, int chunk) {
    return tbase + row * 64 + ((chunk ^ ((row >> 1) & 3)) << 4);
}

// ---------------------------------------------------------------------------
// HMMA GEMM (NT), 3-stage cp.async pipeline, ONE barrier per K-step.
// CTA 128x128, 8 warps (warp tile 64x32), K-step 32.
// ---------------------------------------------------------------------------
#define TILE_A_H 0
#define TILE_A_L 8192
#define TILE_B_H 16384
#define TILE_B_L 24576
#define STAGE_SZ 32768
#define NSTAGE   3
#define GEMM_SMEM (NSTAGE * STAGE_SZ)

__device__ __forceinline__ void load_stage(
    uint32_t sbase, int tid,
    const __half* __restrict__ Ahp, const __half* __restrict__ Alp,
    const __half* __restrict__ Bhp, const __half* __restrict__ Blp,
    int Kt, int k0)
{
#pragma unroll
    for (int i = 0; i < 2; i++) {
        const int idx  = tid + i * 256;
        const int row  = idx >> 2;
        const int c    = idx & 3;
        const uint32_t sw = (uint32_t)(row * 64 + ((c ^ ((row >> 1) & 3)) << 4));
        const size_t g = (size_t)row * Kt + k0 + c * 8;
        cp16(sbase + TILE_A_H + sw, Ahp + g);
        cp16(sbase + TILE_A_L + sw, Alp + g);
        cp16(sbase + TILE_B_H + sw, Bhp + g);
        cp16(sbase + TILE_B_L + sw, Blp + g);
    }
    cp_commit();
}

__global__ __launch_bounds__(256, 2)
void gemm_hmma(const __half* __restrict__ Ah, const __half* __restrict__ Al,
               const __half* __restrict__ Bh, const __half* __restrict__ Bl,
               float* __restrict__ C,
               int Kt, long long aB, long long bB, long long cB, int ldc)
{
    extern __shared__ __align__(128) char smem[];
    const uint32_t sb = smem_u32(smem);
    const int tid  = threadIdx.x;
    const int warp = tid >> 5;
    const int lane = tid & 31;
    const int b    = blockIdx.z;
    const int rA0  = blockIdx.y * 128;
    const int rB0  = blockIdx.x * 128;

    const __half* Ahp = Ah + (size_t)b * aB + (size_t)rA0 * Kt;
    const __half* Alp = Al + (size_t)b * aB + (size_t)rA0 * Kt;
    const __half* Bhp = Bh + (size_t)b * bB + (size_t)rB0 * Kt;
    const __half* Blp = Bl + (size_t)b * bB + (size_t)rB0 * Kt;

    const int warp_m = (warp >> 2) << 6;
    const int warp_n = (warp & 3) << 5;

    float acc[4][4][4];
#pragma unroll
    for (int i = 0; i < 4; i++)
#pragma unroll
        for (int j = 0; j < 4; j++)
#pragma unroll
            for (int q = 0; q < 4; q++) acc[i][j][q] = 0.f;

    const int arow = lane & 15;
    const int acx  = (lane >> 4) & 1;
    const int brow = (lane & 7) + ((lane & 16) >> 1);
    const int bcx  = (lane >> 3) & 1;

    const int T = Kt >> 5;
    // preload stages 0 and 1
    load_stage(sb, tid, Ahp, Alp, Bhp, Blp, Kt, 0);
    load_stage(sb + STAGE_SZ, tid, Ahp, Alp, Bhp, Blp, Kt, 32);

    int stg = 0;
    for (int t = 0; t < T; t++) {
        if (t + 2 < T) cp_wait<1>(); else cp_wait<0>();
        __syncthreads();   // stage t resident + WAR protection for prefetch below

        const uint32_t st = sb + (uint32_t)stg * STAGE_SZ;
#pragma unroll
        for (int kk = 0; kk < 2; kk++) {
            uint32_t AH[4][4], AL[4][4], BH[2][4], BL[2][4];
            const int ac = kk * 2 + acx;
            const int bc = kk * 2 + bcx;
#pragma unroll
            for (int i = 0; i < 4; i++) {
                ldsm4(AH[i], tadr(st + TILE_A_H, warp_m + i * 16 + arow, ac));
                ldsm4(AL[i], tadr(st + TILE_A_L, warp_m + i * 16 + arow, ac));
            }
#pragma unroll
            for (int j = 0; j < 2; j++) {
                ldsm4(BH[j], tadr(st + TILE_B_H, warp_n + j * 16 + brow, bc));
                ldsm4(BL[j], tadr(st + TILE_B_L, warp_n + j * 16 + brow, bc));
            }
#pragma unroll
            for (int i = 0; i < 4; i++)
#pragma unroll
                for (int j = 0; j < 4; j++) {
                    const uint32_t bh0 = BH[j >> 1][(j & 1) * 2];
                    const uint32_t bh1 = BH[j >> 1][(j & 1) * 2 + 1];
                    const uint32_t bl0 = BL[j >> 1][(j & 1) * 2];
                    const uint32_t bl1 = BL[j >> 1][(j & 1) * 2 + 1];
                    mma16816(acc[i][j], AH[i], bh0, bh1);   // hi*hi
                    mma16816(acc[i][j], AH[i], bl0, bl1);   // hi*lo
                    mma16816(acc[i][j], AL[i], bh0, bh1);   // lo*hi
                }
        }

        if (t + 2 < T) {
            int ps = stg + 2; if (ps >= NSTAGE) ps -= NSTAGE;
            load_stage(sb + (uint32_t)ps * STAGE_SZ, tid,
                       Ahp, Alp, Bhp, Blp, Kt, (t + 2) << 5);
        }
        if (++stg == NSTAGE) stg = 0;
    }

    float* Cb = C + (size_t)b * cB;
    const int tr = lane >> 2;
    const int tc = (lane & 3) * 2;
#pragma unroll
    for (int i = 0; i < 4; i++) {
#pragma unroll
        for (int j = 0; j < 4; j++) {
            const int row = rA0 + warp_m + i * 16 + tr;
            const int col = rB0 + warp_n + j * 8 + tc;
            *reinterpret_cast<float2*>(Cb + (size_t)row * ldc + col) =
                make_float2(acc[i][j][0], acc[i][j][1]);
            *reinterpret_cast<float2*>(Cb + (size_t)(row + 8) * ldc + col) =
                make_float2(acc[i][j][2], acc[i][j][3]);
        }
    }
}

// ---------------------------------------------------------------------------
// fp32 -> fp16 hi/lo split, vectorized grid-stride
// ---------------------------------------------------------------------------
__global__ __launch_bounds__(256)
void split_kernel(const float* __restrict__ x,
                  __half* __restrict__ xh, __half* __restrict__ xl, int n4)
{
    const int stride = gridDim.x * blockDim.x;
    for (int i = blockIdx.x * blockDim.x + threadIdx.x; i < n4; i += stride) {
        const float4 v = reinterpret_cast<const float4*>(x)[i];
        const __half h0 = __float2half_rn(v.x), h1 = __float2half_rn(v.y);
        const __half h2 = __float2half_rn(v.z), h3 = __float2half_rn(v.w);
        const __half l0 = __float2half_rn(v.x - __half2float(h0));
        const __half l1 = __float2half_rn(v.y - __half2float(h1));
        const __half l2 = __float2half_rn(v.z - __half2float(h2));
        const __half l3 = __float2half_rn(v.w - __half2float(h3));
        __half2* hp = reinterpret_cast<__half2*>(xh) + i * 2;
        __half2* lp = reinterpret_cast<__half2*>(xl) + i * 2;
        hp[0] = __halves2half2(h0, h1);  hp[1] = __halves2half2(h2, h3);
        lp[0] = __halves2half2(l0, l1);  lp[1] = __halves2half2(l2, l3);
    }
}

// ---------------------------------------------------------------------------
// Transpose: St[b, m, n] = S[b, n, m]
// ---------------------------------------------------------------------------
__global__ __launch_bounds__(256)
void transpose_kernel(const float* __restrict__ S, float* __restrict__ St)
{
    __shared__ float t[32][33];
    const int b  = blockIdx.z;
    const int n0 = blockIdx.y * 32;
    const int m0 = blockIdx.x * 32;
    const float* Sp  = S  + (size_t)b * N_ * M_;
    float*       Stp = St + (size_t)b * N_ * M_;
    const int x = threadIdx.x, y = threadIdx.y;
#pragma unroll
    for (int j = 0; j < 32; j += 8)
        t[y + j][x] = Sp[(size_t)(n0 + y + j) * M_ + m0 + x];
    __syncthreads();
#pragma unroll
    for (int j = 0; j < 32; j += 8)
        Stp[(size_t)(m0 + y + j) * N_ + n0 + x] = t[x][y + j];
}

// ---------------------------------------------------------------------------
// Fused masked softmax + sparse apply:
//   p = softmax(mask ? S[row,:] : -inf);  out[row,:] = sum_{k: p_k > TAU} p_k * X[k,:]
// Softmax of sigma=32 logits is near-one-hot (3-6 significant terms).
// Deterministic list via warp-ballot prefix; exact fp32 gather-accumulate.
// ---------------------------------------------------------------------------
#define TAU 1e-7f

__global__ __launch_bounds__(256)
void softmax_apply(const float* __restrict__ S, const int* __restrict__ mask,
                   const float* __restrict__ X, float* __restrict__ out)
{
    __shared__ float se[512];
    __shared__ float sp[512];
    __shared__ int   sidx[512];
    __shared__ float red[8];
    __shared__ float bcast;
    __shared__ int   scnt;

    const int row = blockIdx.x;          // 0 .. B*512-1
    const int b   = row >> 9;
    const float* Sr = S + (size_t)row * 512;
    const int*   mk = mask + (size_t)b * 512;
    const float* Xb = X + (size_t)b * 512 * D_;
    const int t    = threadIdx.x;
    const int lane = t & 31;
    const int warp = t >> 5;

    const int m0 = mk[t];
    const int m1 = mk[t + 256];
    const float v0 = m0 ? Sr[t]       : -INFINITY;
    const float v1 = m1 ? Sr[t + 256] : -INFINITY;

    // block max
    float mx = fmaxf(v0, v1);
#pragma unroll
    for (int s = 16; s > 0; s >>= 1) mx = fmaxf(mx, __shfl_xor_sync(0xffffffffu, mx, s));
    if (lane == 0) red[warp] = mx;
    __syncthreads();
    if (t == 0) {
        float m = red[0];
#pragma unroll
        for (int k = 1; k < 8; k++) m = fmaxf(m, red[k]);
        bcast = m;
    }
    __syncthreads();
    mx = bcast;

    const float e0 = m0 ? __expf(v0 - mx) : 0.f;
    const float e1 = m1 ? __expf(v1 - mx) : 0.f;
    se[t] = e0;  se[t + 256] = e1;

    // block sum
    float sm = e0 + e1;
#pragma unroll
    for (int s = 16; s > 0; s >>= 1) sm += __shfl_xor_sync(0xffffffffu, sm, s);
    if (lane == 0) red[warp] = sm;
    __syncthreads();
    if (t == 0) {
        float s = red[0];
#pragma unroll
        for (int k = 1; k < 8; k++) s += red[k];
        bcast = 1.f / s;
    }
    __syncthreads();
    const float inv = bcast;

    // warp 0 builds deterministic significant list
    if (t < 32) {
        int base = 0;
#pragma unroll
        for (int j = 0; j < 16; j++) {
            const float p = se[j * 32 + t] * inv;
            const bool sig = p > TAU;
            const unsigned bm = __ballot_sync(0xffffffffu, sig);
            if (sig) {
                const int pos = base + __popc(bm & ((1u << t) - 1u));
                sidx[pos] = j * 32 + t;
                sp[pos]   = p;
            }
            base += __popc(bm);
        }
        if (t == 0) scnt = base;
    }
    __syncthreads();

    const int cnt = scnt;
    float4 acc = make_float4(0.f, 0.f, 0.f, 0.f);
    for (int i = 0; i < cnt; i++) {
        const float p = sp[i];
        const float4 xv = *reinterpret_cast<const float4*>(Xb + (size_t)sidx[i] * D_ + t * 4);
        acc.x += p * xv.x;  acc.y += p * xv.y;
        acc.z += p * xv.z;  acc.w += p * xv.w;
    }
    *reinterpret_cast<float4*>(out + (size_t)row * D_ + t * 4) = acc;
}

// ---------------------------------------------------------------------------
extern "C" void kernel_launch(void* const* d_in, const int* in_sizes, int n_in,
                              void* d_out, int out_size)
{
    const float* x1    = (const float*)d_in[0];
    const float* x2    = (const float*)d_in[1];
    const int*   mask1 = (const int*)  d_in[2];
    const int*   mask2 = (const int*)  d_in[3];

    float* out     = (float*)d_out;
    float* x1_coef = out;
    float* x2_coef = out + (size_t)B_ * N_ * D_;

    float *S, *St;
    __half *x1h, *x1l, *x2h, *x2l;
    cudaGetSymbolAddress((void**)&S,   g_S);
    cudaGetSymbolAddress((void**)&St,  g_St);
    cudaGetSymbolAddress((void**)&x1h, g_x1h);  cudaGetSymbolAddress((void**)&x1l, g_x1l);
    cudaGetSymbolAddress((void**)&x2h, g_x2h);  cudaGetSymbolAddress((void**)&x2l, g_x2l);

    cudaFuncSetAttribute(gemm_hmma, cudaFuncAttributeMaxDynamicSharedMemorySize, GEMM_SMEM);

    // 1) fp16 hi/lo splits
    split_kernel<<<1184, 256>>>(x1, x1h, x1l, B_ * N_ * D_ / 4);
    split_kernel<<<1184, 256>>>(x2, x2h, x2l, B_ * M_ * D_ / 4);

    // 2) S = x1 @ x2^T  (raw logits, fp32)
    gemm_hmma<<<dim3(M_ / 128, N_ / 128, B_), 256, GEMM_SMEM>>>(
        x1h, x1l, x2h, x2l, S, D_,
        (long long)N_ * D_, (long long)M_ * D_, (long long)N_ * M_, M_);

    // 3) St = S^T (raw logits, [m, n])
    transpose_kernel<<<dim3(M_ / 32, N_ / 32, B_), dim3(32, 8)>>>(S, St);

    // 4) fused masked-softmax + near-one-hot sparse apply, both directions
    softmax_apply<<<B_ * N_, 256>>>(S,  mask2, x2, x1_coef);
    softmax_apply<<<B_ * M_, 256>>>(St, mask1, x1, x2_coef);
}